// round 7
// baseline (speedup 1.0000x reference)
#include <cuda_runtime.h>
#include <cstdint>

// ----------------------------------------------------------------------------
// TitleGenerator fused single kernel. 148 persistent CTAs x 608 threads,
// 13-14 batch rows each.
//  Phase A (once): build combined weight rows [0,320) in SMEM, compute
//    ht = leaky(img @ lin1_w.T + b1) for this CTA's rows.
//  Phase B (400 steps): matvec [608x128] @ x, j-packed f32x2 (weights are
//    native b64 pairs, zero packing MOVs), GRU gates, char outputs.
//    Rows [320,608) stream raw weights from L2. Period-2 bitwise fixed-point
//    detection -> replicate remaining outputs.
// ----------------------------------------------------------------------------

#define BB      2048
#define HH      128
#define CC      96
#define TSTEPS  400
#define NT      608
#define NROWS_S 320
#define TITLES_ELEMS 78643200        // 2048*400*96

// dynamic smem layout (bytes)
#define OFF_W    0
#define SZ_W     (32 * NROWS_S * 16)           // 163840
#define OFF_XH   (OFF_W + SZ_W)
#define OFF_XL   (OFF_XH + 14 * 128 * 4)
#define OFF_X2   (OFF_XL + 14 * 128 * 4)
#define OFF_GSM  (OFF_X2 + 14 * 128 * 4)       // 185344
#define SZ_GSM   (14 * 608 * 4)                // 34048
#define OFF_M4   (OFF_GSM + SZ_GSM)            // 219392
#define OFF_LEN  (OFF_M4 + 256)
#define SMEM_TOT (OFF_LEN + 64)                // 219712

typedef unsigned long long ull;

__device__ __forceinline__ void upk2(ull v, float& lo, float& hi) {
    asm("mov.b64 {%0, %1}, %2;" : "=f"(lo), "=f"(hi) : "l"(v));
}
#define FMA2(acc, a, b) asm("fma.rn.f32x2 %0, %1, %2, %3;" : "=l"(acc) : "l"(a), "l"(b), "l"(acc))

__global__ __launch_bounds__(608, 1)
void fused_kernel(float* __restrict__ out,
                  const float* __restrict__ img,
                  const float* __restrict__ lin1_w,
                  const float* __restrict__ lin1_b,
                  const float* __restrict__ w_ih,
                  const float* __restrict__ w_hh,
                  const float* __restrict__ b_ih,
                  const float* __restrict__ b_hh,
                  const float* __restrict__ lin2_w,
                  const float* __restrict__ lin2_b,
                  int hasLens) {
    extern __shared__ __align__(16) char smraw[];
    float4* wsm4 = reinterpret_cast<float4*>(smraw + OFF_W);
    float*  xh   = reinterpret_cast<float*>(smraw + OFF_XH);
    float*  xl   = reinterpret_cast<float*>(smraw + OFF_XL);
    float*  xp2  = reinterpret_cast<float*>(smraw + OFF_X2);
    float*  gsm  = reinterpret_cast<float*>(smraw + OFF_GSM);
    float*  m4   = reinterpret_cast<float*>(smraw + OFF_M4);
    int*    lensm= reinterpret_cast<int*>(smraw + OFF_LEN);

    const int tid = threadIdx.x;
    const int bid = blockIdx.x;
    int base, nv;
    if (bid < 124) { base = bid * 14; nv = 14; }
    else           { base = 1736 + (bid - 124) * 13; nv = 13; }

    // ---- Phase A0: fill combined weight rows [0,NROWS_S) into SMEM [j4][i] --
    {
        const float4* wih4 = reinterpret_cast<const float4*>(w_ih);
        const float4* whh4 = reinterpret_cast<const float4*>(w_hh);
        for (int idx = tid; idx < 32 * NROWS_S; idx += NT) {
            int j4 = idx / NROWS_S;
            int i  = idx - j4 * NROWS_S;
            float4 a = wih4[i * 32 + j4];
            if (i < 256) {
                float4 b = whh4[i * 32 + j4];
                a.x += b.x; a.y += b.y; a.z += b.z; a.w += b.w;
            }
            wsm4[idx] = a;
        }
    }
    // per-thread combined bias
    float bias;
    if (tid < 256)      bias = b_ih[tid] + b_hh[tid];
    else if (tid < 384) bias = b_ih[tid];
    else if (tid < 512) bias = b_hh[tid - 128];
    else                bias = lin2_b[tid - 512];

    // zero x buffers, lens
    for (int m = tid; m < 14 * 128; m += NT) { xh[m] = 0.f; xl[m] = 0.f; xp2[m] = 0.f; }
    if (tid < 16) lensm[tid] = 0;

    // ---- Phase A1: lin1 — ht rows for this CTA (staged in gsm) -------------
    {
        const int j  = tid & 127;
        const int ks = tid >> 7;          // 0..3 for tid<512
        ull acc[14];
#pragma unroll
        for (int r = 0; r < 14; r++) acc[r] = 0ull;

        float4*       xs4 = reinterpret_cast<float4*>(gsm);       // stage: 14 x 64 float4
        const float4* im4 = reinterpret_cast<const float4*>(img);
        const ulonglong2* xs2 = reinterpret_cast<const ulonglong2*>(gsm);

        for (int kc = 0; kc < 16; kc++) {
            __syncthreads();
            for (int m = tid; m < 14 * 64; m += NT) {
                int r = m >> 6, kk4 = m & 63;
                float4 v = make_float4(0.f, 0.f, 0.f, 0.f);
                if (r < nv) v = im4[(size_t)(base + r) * 1024 + kc * 64 + kk4];
                xs4[r * 64 + kk4] = v;
            }
            __syncthreads();
            if (tid < 512) {
                const ulonglong2* wl = reinterpret_cast<const ulonglong2*>(
                    lin1_w + (size_t)j * 4096 + kc * 256 + ks * 64);
#pragma unroll 4
                for (int q = 0; q < 16; q++) {
                    ulonglong2 wv = wl[q];
#pragma unroll
                    for (int r = 0; r < 14; r++) {
                        ulonglong2 xv = xs2[r * 64 + ks * 16 + q];
                        FMA2(acc[r], wv.x, xv.x);
                        FMA2(acc[r], wv.y, xv.y);
                    }
                }
            }
        }
        __syncthreads();
        if (tid < 512) {
#pragma unroll
            for (int r = 0; r < 14; r++) {
                float lo, hi; upk2(acc[r], lo, hi);
                gsm[r * 512 + ks * 128 + j] = lo + hi;
            }
        }
        __syncthreads();
        for (int m = tid; m < 14 * 128; m += NT) {
            int r = m >> 7, jj = m & 127;
            float v = gsm[r * 512 + jj] + gsm[r * 512 + 128 + jj]
                    + gsm[r * 512 + 256 + jj] + gsm[r * 512 + 384 + jj] + lin1_b[jj];
            xh[r * 128 + jj] = (v >= 0.f) ? v : 0.01f * v;
        }
        __syncthreads();
    }

    // x source (16B granules, row stride 32)
    const ulonglong2* xb = (tid < 512) ? reinterpret_cast<const ulonglong2*>(xh)
                                       : reinterpret_cast<const ulonglong2*>(xl);

    // streamed raw weight row for tid >= NROWS_S
    const ulonglong2* wrow = nullptr;
    if (tid >= NROWS_S) {
        const float* p;
        if (tid < 384)      p = w_ih  + (size_t)tid * 128;
        else if (tid < 512) p = w_hh  + (size_t)(tid - 128) * 128;
        else                p = lin2_w + (size_t)(tid - 512) * 128;
        wrow = reinterpret_cast<const ulonglong2*>(p);
    }
    const ulonglong2* wsm2 = reinterpret_cast<const ulonglong2*>(wsm4);

    // one 4-wide weight granule against all 14 rows
#define ROWS14(WV, J4)                                        \
    _Pragma("unroll")                                         \
    for (int r = 0; r < 14; r++) {                            \
        ulonglong2 xv = xb[r * 32 + (J4)];                    \
        FMA2(acc[r], (WV).x, xv.x);                           \
        FMA2(acc[r], (WV).y, xv.y);                           \
    }

    auto writeacc = [&](ull* acc) {
#pragma unroll
        for (int r = 0; r < 14; r++) {
            float lo, hi; upk2(acc[r], lo, hi);
            gsm[r * 608 + tid] = lo + hi + bias;
        }
    };

    auto matvec = [&]() {
        ull acc[14];
#pragma unroll
        for (int r = 0; r < 14; r++) acc[r] = 0ull;
        if (tid < NROWS_S) {
#pragma unroll 4
            for (int j4 = 0; j4 < 32; j4++) {
                ulonglong2 wv = wsm2[j4 * NROWS_S + tid];
                ROWS14(wv, j4)
            }
        } else {
#pragma unroll 1
            for (int blk = 0; blk < 8; blk++) {
                ulonglong2 w0 = wrow[blk * 4 + 0];
                ulonglong2 w1 = wrow[blk * 4 + 1];
                ulonglong2 w2 = wrow[blk * 4 + 2];
                ulonglong2 w3 = wrow[blk * 4 + 3];
                ROWS14(w0, blk * 4 + 0)
                ROWS14(w1, blk * 4 + 1)
                ROWS14(w2, blk * 4 + 2)
                ROWS14(w3, blk * 4 + 3)
            }
        }
        writeacc(acc);
    };

    // step-1 matvec: gates from raw w_ih (h=0), lin2/hn rows = bias only
    auto matvec1 = [&]() {
        ull acc[14];
#pragma unroll
        for (int r = 0; r < 14; r++) acc[r] = 0ull;
        if (tid < 384) {
            const ulonglong2* wr = reinterpret_cast<const ulonglong2*>(w_ih + (size_t)tid * 128);
#pragma unroll 1
            for (int blk = 0; blk < 8; blk++) {
                ulonglong2 w0 = wr[blk * 4 + 0];
                ulonglong2 w1 = wr[blk * 4 + 1];
                ulonglong2 w2 = wr[blk * 4 + 2];
                ulonglong2 w3 = wr[blk * 4 + 3];
                ROWS14(w0, blk * 4 + 0)
                ROWS14(w1, blk * 4 + 1)
                ROWS14(w2, blk * 4 + 2)
                ROWS14(w3, blk * 4 + 3)
            }
        }
        writeacc(acc);
    };

    // GRU gates + state rotation + per-row char maxima (4 partials per row)
    auto gatephase = [&](bool step1) -> bool {
        bool changed = false;
        for (int m = tid; m < 14 * HH; m += NT) {
            int r = m >> 7, k = m & 127;
            if (r < nv) {
                float rpre = gsm[r * 608 + k];
                float zpre = gsm[r * 608 + 128 + k];
                float inp  = gsm[r * 608 + 256 + k];
                float hnp  = gsm[r * 608 + 384 + k];
                float rg = __fdividef(1.0f, 1.0f + __expf(-rpre));
                float zg = __fdividef(1.0f, 1.0f + __expf(-zpre));
                float n  = tanhf(inp + rg * hnp);
                int   xi = r * 128 + k;
                float xold = xh[xi];
                float old2 = xp2[xi];
                float hn = step1 ? (1.0f - zg) * n
                                 : (1.0f - zg) * n + zg * xold;
                changed |= (__float_as_int(hn) != __float_as_int(old2));
                xp2[xi] = xold;
                xh[xi]  = hn;
                xl[xi]  = (hn >= 0.f) ? hn : 0.01f * hn;
            }
        }
        if (tid < 56) {
            int r = tid >> 2, q = tid & 3;
            float mx = -3.4e38f;
#pragma unroll
            for (int c = 0; c < 24; c++) mx = fmaxf(mx, gsm[r * 608 + 512 + q * 24 + c]);
            m4[tid] = mx;
        }
        return changed;
    };

    const float THR = (float)(1.0 - 1e-05);

    // pre-step: hn0 = GRU(ht, 0)
    matvec1();
    __syncthreads();
    gatephase(true);
    __syncthreads();

    float cval[3], pval[3];
    int   foff[3];
    int   nslots = 0;
    int   sConv = -1;

    for (int s = 0; s < TSTEPS; s++) {
        matvec();
        __syncthreads();
        bool changed = gatephase(false);
        if (s == 0) changed = true;               // xp2 invalid at s=0
        int cnt = __syncthreads_count(changed ? 1 : 0);

        // chars_s from lin2 rows of gsm
#pragma unroll
        for (int q = 0; q < 3; q++) pval[q] = cval[q];
        nslots = 0;
        for (int m = tid; m < nv * CC; m += NT) {
            int r = m / CC, c = m - r * CC;
            float mx = fmaxf(fmaxf(m4[r * 4 + 0], m4[r * 4 + 1]),
                             fmaxf(m4[r * 4 + 2], m4[r * 4 + 3]));
            float ch = gsm[r * 608 + 512 + c];
            float cn = __fdiv_rn(ch, mx);
            float val = (cn > THR) ? cn : 0.f;
            int off = (base + r) * (TSTEPS * CC) + c;
            out[(size_t)off + (size_t)s * CC] = val;
            if (c == 52 && val == 1.0f && lensm[r] == 0) lensm[r] = s + 1;
            cval[nslots] = val;
            foff[nslots] = off;
            nslots++;
        }

        if (cnt == 0) { sConv = s; break; }
        __syncthreads();
    }

    if (sConv >= 0) {
        // period-2 fixed point: outputs alternate between steps sConv-1, sConv
        for (int s2 = sConv + 1; s2 < TSTEPS; s2++) {
            bool even = (((s2 - sConv) & 1) == 0);
#pragma unroll
            for (int q = 0; q < 3; q++) {
                if (q < nslots)
                    out[(size_t)foff[q] + (size_t)s2 * CC] = even ? cval[q] : pval[q];
            }
        }
    }

    __syncthreads();
    if (hasLens && tid < nv) {
        int L = lensm[tid];
        out[(size_t)TITLES_ELEMS + base + tid] = (float)(L == 0 ? TSTEPS : L);
    }
}

// ------------------------------- launch -------------------------------------
extern "C" void kernel_launch(void* const* d_in, const int* in_sizes, int n_in,
                              void* d_out, int out_size) {
    const float* img_feat = (const float*)d_in[0];
    const float* lin1_w   = (const float*)d_in[1];
    const float* lin1_b   = (const float*)d_in[2];
    const float* w_ih     = (const float*)d_in[3];
    const float* w_hh     = (const float*)d_in[4];
    const float* b_ih     = (const float*)d_in[5];
    const float* b_hh     = (const float*)d_in[6];
    const float* lin2_w   = (const float*)d_in[7];
    const float* lin2_b   = (const float*)d_in[8];

    cudaFuncSetAttribute(fused_kernel,
                         cudaFuncAttributeMaxDynamicSharedMemorySize, SMEM_TOT);

    int hasLens = (out_size >= TITLES_ELEMS + BB) ? 1 : 0;
    fused_kernel<<<148, 608, SMEM_TOT>>>((float*)d_out, img_feat, lin1_w, lin1_b,
                                         w_ih, w_hh, b_ih, b_hh, lin2_w, lin2_b,
                                         hasLens);
}